// round 17
// baseline (speedup 1.0000x reference)
#include <cuda_runtime.h>
#include <math.h>

// ---------------------------------------------------------------------------
// GaussianRasterizer — prepass + single raster kernel.
//   gr_prep  : per Gaussian: bbox vector {mx,my,ex,ey} (tile half folded) +
//              eval-ready {mx,my,qa,qb2}/{qc, o*c} with -0.5*log2e folded
//              (weight = 2^q).
//   gr_raster: one CTA per 16x16 tile, 512 threads = 4 independent
//              128-thread groups over disjoint N-ranges (named barriers).
//              Each thread owns TWO pixels (y and y+8, same x) sharing the
//              dx terms. launch_bounds(512,2) => 64-reg budget (no spills).
//              Fixed-order group combine => bit-deterministic.
// ---------------------------------------------------------------------------

#define TILE_W 16
#define TILE_H 16
#define NT 512
#define NG 4
#define GSZ 128
#define CPT 4
#define GCHUNK (GSZ * CPT)      // 512 >= N/4 for N=2048 => single chunk
#define CAP 128                 // survivor batch capacity per group
#define GW (GSZ / 32)
#define MAXN 8192

__device__ float4 g_bb[MAXN];   // {mx, my, ex, ey} (ex,ey include tile half)
__device__ float4 g_p0[MAXN];   // {mx, my, qa, qb2}
__device__ float4 g_p1[MAXN];   // {qc, o*cr, o*cg, o*cb}

__device__ __forceinline__ float scalar_as_float(const int* p) {
    int v = *p;
    if (v >= 0 && v <= 1000000) return (float)v;
    return __int_as_float(v);
}

__device__ __forceinline__ float ex2(float q) {
    float r;
    asm("ex2.approx.ftz.f32 %0, %1;" : "=f"(r) : "f"(q));
    return r;
}

__device__ __forceinline__ void bar_group(int id) {
    asm volatile("bar.sync %0, %1;" :: "r"(id), "n"(GSZ) : "memory");
}

__global__ __launch_bounds__(256)
void gr_prep(const float* __restrict__ opacity,
             const float* __restrict__ means,
             const float* __restrict__ stds,
             const float* __restrict__ rhos,
             const float* __restrict__ colors,
             const int*   __restrict__ scale_p,
             const int*   __restrict__ ratio_p,
             int N) {
    const int i = blockIdx.x * blockDim.x + threadIdx.x;
    if (i >= N) return;

    const float s    = scalar_as_float(scale_p);
    const float r    = scalar_as_float(ratio_p);
    const float rs   = r * s;
    const float HL2E = -0.5f * 1.44269504088896340736f;   // -0.5*log2(e)

    float2 mn = ((const float2*)means)[i];
    float2 st = ((const float2*)stds)[i];
    float rho = rhos[i];
    float o   = opacity[i];
    float c0  = colors[3 * i + 0];
    float c1  = colors[3 * i + 1];
    float c2  = colors[3 * i + 2];

    float sx = st.x * s;
    float sy = st.y * s;
    float om = 1.0f - rho * rho;
    float qa  = __fdividef(HL2E,               sx * sx * om);
    float qc  = __fdividef(HL2E,               sy * sy * om);
    float qb2 = __fdividef(-2.0f * HL2E * rho, sx * sy * om);

    g_bb[i] = make_float4(mn.x, mn.y,
                          fmaf(rs, st.x, (TILE_W - 1) * 0.5f),
                          fmaf(rs, st.y, (TILE_H - 1) * 0.5f));
    g_p0[i] = make_float4(mn.x, mn.y, qa, qb2);
    g_p1[i] = make_float4(qc, o * c0, o * c1, o * c2);
}

__global__ __launch_bounds__(NT, 2)
void gr_raster(const int* __restrict__ ratio_p,
               float* __restrict__ out, int N, int W, int H) {
    __shared__ float4 s0[NG][CAP];
    __shared__ float4 s1[NG][CAP];
    __shared__ int    swc[NG][GW];
    __shared__ float  sacc[NG - 1][GSZ][6];   // 2 px x RGB per thread

    const int tid   = threadIdx.x;
    const int lane  = tid & 31;
    const int g     = tid >> 7;           // group 0..3
    const int htid  = tid & (GSZ - 1);    // 0..127 within group
    const int gwid  = htid >> 5;
    const int barid = g + 1;

    // Two pixels per thread: (px, py0) and (px, py0+8).
    const int px  = blockIdx.x * TILE_W + (htid & (TILE_W - 1));
    const int py0 = blockIdx.y * TILE_H + (htid >> 4);       // rows 0..7
    const int py1 = py0 + 8;                                  // rows 8..15
    const float x  = (float)px + 0.5f;
    const float y0 = (float)py0 + 0.5f;

    const float tcx = (float)(blockIdx.x * TILE_W) + 0.5f + (TILE_W - 1) * 0.5f;
    const float tcy = (float)(blockIdx.y * TILE_H) + 0.5f + (TILE_H - 1) * 0.5f;

    const float r    = scalar_as_float(ratio_p);
    const float HL2E = -0.5f * 1.44269504088896340736f;
    const float cth  = HL2E * r * r;      // pass when folded q >= cth

    const int N4  = (N + NG - 1) / NG;
    const int beg = g * N4;
    const int end = min(N, beg + N4);

    float ar0 = 0.f, ag0 = 0.f, ab0 = 0.f;   // stream A, pixel 0/1 pairs
    float ar1 = 0.f, ag1 = 0.f, ab1 = 0.f;
    float br0 = 0.f, bg0 = 0.f, bb0 = 0.f;   // stream B
    float br1 = 0.f, bg1 = 0.f, bb1 = 0.f;

    for (int base = beg; base < end; base += GCHUNK) {
        // ---- Cull: CPT candidates per thread, 1 LDG.128 each.
        const int ib = base + htid * CPT;
        unsigned hm = 0;
        #pragma unroll
        for (int k = 0; k < CPT; k++) {
            int i = ib + k;
            if (i < end) {
                float4 bb = g_bb[i];
                bool hit = (fabsf(bb.x - tcx) <= bb.z) &
                           (fabsf(bb.y - tcy) <= bb.w);
                if (hit) hm |= (1u << k);
            }
        }
        int cnt = __popc(hm);

        // ---- 3-ballot prefix scan (cnt in 0..4).
        unsigned bb0m = __ballot_sync(0xffffffffu, cnt & 1);
        unsigned bb1m = __ballot_sync(0xffffffffu, (cnt >> 1) & 1);
        unsigned bb2m = __ballot_sync(0xffffffffu, (cnt >> 2) & 1);
        unsigned lt = (1u << lane) - 1u;
        int excl = __popc(bb0m & lt) + 2 * __popc(bb1m & lt) + 4 * __popc(bb2m & lt);
        if (lane == 31) swc[g][gwid] = excl + cnt;
        bar_group(barid);

        int off = 0, total = 0;
        #pragma unroll
        for (int w = 0; w < GW; w++) {
            int c = swc[g][w];
            if (w < gwid) off += c;
            total += c;
        }
        const int slot0 = off + excl;

        // ---- Capacity-batched compaction + eval (1 batch in practice).
        for (int done = 0; done < total; done += CAP) {
            const int btot = min(total - done, CAP);

            {
                int slot = slot0;
                unsigned m = hm;
                while (m) {
                    int k = __ffs(m) - 1;
                    m &= m - 1;
                    int rel = slot - done;
                    if (rel >= 0 && rel < CAP) {
                        int i = ib + k;
                        s0[g][rel] = g_p0[i];
                        s1[g][rel] = g_p1[i];
                    }
                    slot++;
                }
            }
            bar_group(barid);              // survivor batch ready

            // ---- Eval: dual-gaussian streams, 2 pixels each, shared dx.
            int j = 0;
            for (; j + 1 < btot; j += 2) {
                float4 aA = s0[g][j],     bA = s1[g][j];
                float4 aB = s0[g][j + 1], bB = s1[g][j + 1];

                // Stream A
                float dxA  = x  - aA.x;
                float dyA0 = y0 - aA.y;
                float dyA1 = dyA0 + 8.0f;
                float vA   = aA.w * dxA;
                float baseA = (aA.z * dxA) * dxA;
                float qA0 = fmaf(dyA0, fmaf(bA.x, dyA0, vA), baseA);
                float qA1 = fmaf(dyA1, fmaf(bA.x, dyA1, vA), baseA);

                // Stream B
                float dxB  = x  - aB.x;
                float dyB0 = y0 - aB.y;
                float dyB1 = dyB0 + 8.0f;
                float vB   = aB.w * dxB;
                float baseB = (aB.z * dxB) * dxB;
                float qB0 = fmaf(dyB0, fmaf(bB.x, dyB0, vB), baseB);
                float qB1 = fmaf(dyB1, fmaf(bB.x, dyB1, vB), baseB);

                float wA0 = ex2(qA0); wA0 = (qA0 >= cth) ? wA0 : 0.0f;
                float wA1 = ex2(qA1); wA1 = (qA1 >= cth) ? wA1 : 0.0f;
                float wB0 = ex2(qB0); wB0 = (qB0 >= cth) ? wB0 : 0.0f;
                float wB1 = ex2(qB1); wB1 = (qB1 >= cth) ? wB1 : 0.0f;

                ar0 = fmaf(wA0, bA.y, ar0);
                ag0 = fmaf(wA0, bA.z, ag0);
                ab0 = fmaf(wA0, bA.w, ab0);
                ar1 = fmaf(wA1, bA.y, ar1);
                ag1 = fmaf(wA1, bA.z, ag1);
                ab1 = fmaf(wA1, bA.w, ab1);
                br0 = fmaf(wB0, bB.y, br0);
                bg0 = fmaf(wB0, bB.z, bg0);
                bb0 = fmaf(wB0, bB.w, bb0);
                br1 = fmaf(wB1, bB.y, br1);
                bg1 = fmaf(wB1, bB.z, bg1);
                bb1 = fmaf(wB1, bB.w, bb1);
            }
            if (j < btot) {
                float4 aA = s0[g][j], bA = s1[g][j];
                float dxA  = x  - aA.x;
                float dyA0 = y0 - aA.y;
                float dyA1 = dyA0 + 8.0f;
                float vA   = aA.w * dxA;
                float baseA = (aA.z * dxA) * dxA;
                float qA0 = fmaf(dyA0, fmaf(bA.x, dyA0, vA), baseA);
                float qA1 = fmaf(dyA1, fmaf(bA.x, dyA1, vA), baseA);
                float wA0 = ex2(qA0); wA0 = (qA0 >= cth) ? wA0 : 0.0f;
                float wA1 = ex2(qA1); wA1 = (qA1 >= cth) ? wA1 : 0.0f;
                ar0 = fmaf(wA0, bA.y, ar0);
                ag0 = fmaf(wA0, bA.z, ag0);
                ab0 = fmaf(wA0, bA.w, ab0);
                ar1 = fmaf(wA1, bA.y, ar1);
                ag1 = fmaf(wA1, bA.z, ag1);
                ab1 = fmaf(wA1, bA.w, ab1);
            }
            bar_group(barid);              // batch consumed
        }
    }

    // Merge streams (fixed order A then B).
    const float pr0 = ar0 + br0, pg0 = ag0 + bg0, pb0 = ab0 + bb0;
    const float pr1 = ar1 + br1, pg1 = ag1 + bg1, pb1 = ab1 + bb1;

    // ---- Deterministic combine: groups 1..3 publish; group 0 sums in order.
    if (g) {
        sacc[g - 1][htid][0] = pr0;
        sacc[g - 1][htid][1] = pg0;
        sacc[g - 1][htid][2] = pb0;
        sacc[g - 1][htid][3] = pr1;
        sacc[g - 1][htid][4] = pg1;
        sacc[g - 1][htid][5] = pb1;
    }
    __syncthreads();
    if (g == 0) {
        float sr0 = pr0, sg0 = pg0, sb0 = pb0;
        float sr1 = pr1, sg1 = pg1, sb1 = pb1;
        #pragma unroll
        for (int q = 0; q < NG - 1; q++) {
            sr0 += sacc[q][htid][0];
            sg0 += sacc[q][htid][1];
            sb0 += sacc[q][htid][2];
            sr1 += sacc[q][htid][3];
            sg1 += sacc[q][htid][4];
            sb1 += sacc[q][htid][5];
        }
        if (px < W && py0 < H) {
            int o = (py0 * W + px) * 3;
            out[o + 0] = sr0;
            out[o + 1] = sg0;
            out[o + 2] = sb0;
        }
        if (px < W && py1 < H) {
            int o = (py1 * W + px) * 3;
            out[o + 0] = sr1;
            out[o + 1] = sg1;
            out[o + 2] = sb1;
        }
    }
}

extern "C" void kernel_launch(void* const* d_in, const int* in_sizes, int n_in,
                              void* d_out, int out_size) {
    const float* opacity = (const float*)d_in[0];
    const float* means   = (const float*)d_in[1];
    const float* stds    = (const float*)d_in[2];
    const float* rhos    = (const float*)d_in[3];
    const float* colors  = (const float*)d_in[4];
    const int*   scale_p = (const int*)d_in[7];
    const int*   ratio_p = (const int*)d_in[8];

    int N = in_sizes[0];
    if (N > MAXN) N = MAXN;

    int hw = out_size / 3;
    int W = (int)lrint(sqrt((double)hw));
    while (W > 1 && (hw % W) != 0) W--;
    int H = hw / W;

    float* out = (float*)d_out;

    gr_prep<<<(N + 255) / 256, 256>>>(opacity, means, stds, rhos, colors,
                                      scale_p, ratio_p, N);

    dim3 grid((W + TILE_W - 1) / TILE_W, (H + TILE_H - 1) / TILE_H);
    gr_raster<<<grid, NT>>>(ratio_p, out, N, W, H);
}